// round 17
// baseline (speedup 1.0000x reference)
#include <cuda_runtime.h>
#include <math.h>

#define BB 8
#define CC 12
#define NN 785
#define SS 784
#define HH 28
#define DD 768
#define PATCH 84
#define NTOPK (BB * CC)

// Scratch (allocation-free: __device__ globals; zero-initialized at load)
__device__ float         g_newscore[BB * CC * SS];
__device__ unsigned char g_sel[BB * CC * SS];
__device__ float         g_u[BB * 512];
__device__ float         g_pwa[BB];
__device__ int           g_patchidx[BB * 64];
__device__ unsigned      g_done[BB];   // monotonic across graph replays

// ---------------------------------------------------------------------------
// Exact k-th-largest over vals[0..n) via MSB-first byte radix, with early exit
// when the boundary bin holds a single candidate. blockDim.x == 256.
// Returns T (k-th largest) and rem = k - count(vals > T).
// ---------------------------------------------------------------------------
__device__ __forceinline__ void radix_select_desc(const unsigned* __restrict__ vals,
                                                  int n, int k,
                                                  unsigned* T_out, int* rem_out) {
    __shared__ unsigned rs_hist[256];
    __shared__ unsigned rs_wsum[8];
    __shared__ unsigned rs_pref;
    __shared__ int      rs_kk;
    __shared__ unsigned rs_own;
    __shared__ unsigned rs_T;
    int tid = threadIdx.x;
    unsigned prefix = 0, pmask = 0;
    int kk = k;
    for (int pass = 0; pass < 4; pass++) {
        int shift = 24 - 8 * pass;
        rs_hist[tid] = 0;
        __syncthreads();
        for (int i = tid; i < n; i += 256) {
            unsigned v = vals[i];
            if ((v & pmask) == prefix)
                atomicAdd(&rs_hist[(v >> shift) & 255u], 1u);
        }
        __syncthreads();
        int w = tid >> 5, l = tid & 31;
        unsigned own = rs_hist[255 - tid];   // descending bins
        unsigned v = own;
        #pragma unroll
        for (int o = 1; o < 32; o <<= 1) {
            unsigned up = __shfl_up_sync(0xffffffffu, v, o);
            if (l >= o) v += up;
        }
        if (l == 31) rs_wsum[w] = v;
        __syncthreads();
        unsigned add = 0;
        #pragma unroll
        for (int ww = 0; ww < 8; ww++) add += (ww < w) ? rs_wsum[ww] : 0u;
        unsigned incl = v + add;
        unsigned excl = incl - own;
        if ((int)incl >= kk && (int)excl < kk) {
            rs_pref = prefix | ((unsigned)(255 - tid) << shift);
            rs_kk   = kk - (int)excl;
            rs_own  = own;
        }
        __syncthreads();
        prefix = rs_pref;
        kk = rs_kk;
        pmask |= (0xFFu << shift);
        if (rs_own == 1u && pass < 3) {
            // unique candidate with this prefix IS the threshold value
            for (int i = tid; i < n; i += 256) {
                unsigned vv = vals[i];
                if ((vv & pmask) == prefix) rs_T = vv;
            }
            __syncthreads();
            prefix = rs_T;
            break;
        }
        if (rs_own == 1u) break;  // pass 3: prefix already the full value
    }
    *T_out = prefix;
    *rem_out = kk;
}

// ---------------------------------------------------------------------------
// Fused kernel: blocks 0..95 = per-(b,c) top-84; last-arriving block per b
// runs the GCN/structure/sort phase. Blocks >= 96 stream-copy hs rows 1..784.
// ---------------------------------------------------------------------------
__global__ void __launch_bounds__(256) fused_kernel(const float* __restrict__ x,
                                                    const float* __restrict__ w1,
                                                    const float4* __restrict__ hid4,
                                                    float4* __restrict__ out4,
                                                    int SEL, int copyA) {
    int blk = blockIdx.x;
    int tid = threadIdx.x;
    const int D4 = DD / 4;        // 192
    const int ND4 = NN * D4;      // 150720
    const int RPB = ND4 - D4;     // rows 1..784 float4s per batch

    if (blk >= NTOPK) {
        // -------- bulk copy of rows 1..784 (independent work), 8 f4/thread ---
        int q = (blk - NTOPK) * 2048 + tid;
        #pragma unroll
        for (int rep = 0; rep < 8; rep++) {
            int qq = q + rep * 256;
            if (qq < copyA) {
                int b = qq / RPB;
                int r = qq - b * RPB;
                int idx = b * ND4 + D4 + r;
                out4[idx] = hid4[idx];
            }
        }
        return;
    }

    int b = blk / CC;
    int c = blk - b * CC;

    __shared__ union {
        struct { unsigned ord[SS]; float sc[SS]; unsigned char selm[SS]; } t;
        struct { float pw[SS]; int cc[SS]; unsigned keys[SS]; } g;
    } U;
    __shared__ int      tk_w[8];
    __shared__ double   dredw[8];
    __shared__ float    fredw[8];
    __shared__ int      iredw[8];
    __shared__ float4   qredw[8];
    __shared__ float    s_mean, s_sv0, s_sv1, s_Pp, s_Pn;
    __shared__ int      s_anchor;
    __shared__ unsigned sel_list[64];
    __shared__ int      sel_cnt;
    __shared__ unsigned s_last;

    // ================= top-k phase =================
    const float* row = x + ((size_t)(b * CC + c) * NN) * NN + 1;  // x[b,c,0,1:]
    for (int s = tid; s < SS; s += 256) {
        float v = row[s];
        U.t.sc[s] = v;
        unsigned u = __float_as_uint(v);
        U.t.ord[s] = (u & 0x80000000u) ? ~u : (u | 0x80000000u);
    }
    __syncthreads();

    unsigned T; int rem;
    radix_select_desc(U.t.ord, SS, PATCH, &T, &rem);

    // tie scan: thread t owns s in [4t, 4t+4), 784 = 4*196
    int cnt = 0;
    if (tid < 196) {
        #pragma unroll
        for (int e = 0; e < 4; e++) cnt += (U.t.ord[4 * tid + e] == T);
    }
    int w = tid >> 5, l = tid & 31;
    int v = cnt;
    #pragma unroll
    for (int o = 1; o < 32; o <<= 1) {
        int up = __shfl_up_sync(0xffffffffu, v, o);
        if (l >= o) v += up;
    }
    if (l == 31) tk_w[w] = v;
    __syncthreads();
    int add = 0;
    #pragma unroll
    for (int ww = 0; ww < 8; ww++) add += (ww < w) ? tk_w[ww] : 0;
    int base = v - cnt + add;

    if (tid < 196) {
        int run = base;
        #pragma unroll
        for (int e = 0; e < 4; e++) {
            int s = 4 * tid + e;
            unsigned o = U.t.ord[s];
            bool sel;
            if (o > T) sel = true;
            else if (o == T) { sel = (run < rem); run++; }
            else sel = false;
            U.t.selm[s] = sel ? 1 : 0;
        }
    }
    __syncthreads();

    float* ns = g_newscore + (b * CC + c) * SS;
    unsigned char* gs = g_sel + (b * CC + c) * SS;
    for (int s = tid; s < SS; s += 256) {
        unsigned char m = U.t.selm[s];
        ns[s] = m ? U.t.sc[s] : U.t.sc[s] * 0.7f;
        gs[s] = m;
    }

    // ================= arrival sync: last block of batch b continues =========
    __threadfence();
    __syncthreads();
    if (tid == 0) s_last = atomicAdd(&g_done[b], 1u) % CC;
    __syncthreads();
    if (s_last != CC - 1) return;
    __threadfence();

    // ================= gcn phase (single block per b) =================
    // pw[s] = mean_c new_score; counts; double sum for mean
    double dsum = 0.0;
    if (tid < 196) {
        float4 acc = make_float4(0.f, 0.f, 0.f, 0.f);
        int c0 = 0, c1 = 0, c2 = 0, c3 = 0;
        #pragma unroll
        for (int cx = 0; cx < CC; cx++) {
            float4 vv = *(const float4*)(g_newscore + (b * CC + cx) * SS + 4 * tid);
            acc.x += vv.x; acc.y += vv.y; acc.z += vv.z; acc.w += vv.w;
            uchar4 mm = *(const uchar4*)(g_sel + (b * CC + cx) * SS + 4 * tid);
            c0 += mm.x; c1 += mm.y; c2 += mm.z; c3 += mm.w;
        }
        float p0 = acc.x / 12.f, p1 = acc.y / 12.f, p2 = acc.z / 12.f, p3 = acc.w / 12.f;
        U.g.pw[4 * tid + 0] = p0; U.g.cc[4 * tid + 0] = c0;
        U.g.pw[4 * tid + 1] = p1; U.g.cc[4 * tid + 1] = c1;
        U.g.pw[4 * tid + 2] = p2; U.g.cc[4 * tid + 2] = c2;
        U.g.pw[4 * tid + 3] = p3; U.g.cc[4 * tid + 3] = c3;
        dsum = (double)p0 + (double)p1 + (double)p2 + (double)p3;
    }
    // warp+cross-warp double reduction
    #pragma unroll
    for (int o = 16; o > 0; o >>= 1) dsum += __shfl_down_sync(0xffffffffu, dsum, o);
    if (l == 0) dredw[w] = dsum;
    __syncthreads();
    if (tid == 0) {
        double t2 = 0.0;
        #pragma unroll
        for (int ww = 0; ww < 8; ww++) t2 += dredw[ww];
        s_mean = (float)(t2 / 784.0);
    }
    __syncthreads();
    float mean = s_mean;

    // anchor = argmax_s (pw>mean ? pw : 0), first occurrence
    float bestv = -3.0e38f;
    int besti = 1 << 30;
    for (int s = tid; s < SS; s += 256) {
        float vv = (U.g.pw[s] > mean) ? U.g.pw[s] : 0.0f;
        if (vv > bestv || (vv == bestv && s < besti)) { bestv = vv; besti = s; }
    }
    #pragma unroll
    for (int o = 16; o > 0; o >>= 1) {
        float ov = __shfl_down_sync(0xffffffffu, bestv, o);
        int   oi = __shfl_down_sync(0xffffffffu, besti, o);
        if (ov > bestv || (ov == bestv && oi < besti)) { bestv = ov; besti = oi; }
    }
    if (l == 0) { fredw[w] = bestv; iredw[w] = besti; }
    __syncthreads();
    if (tid == 0) {
        float bv = fredw[0]; int bi = iredw[0];
        #pragma unroll
        for (int ww = 1; ww < 8; ww++) {
            if (fredw[ww] > bv || (fredw[ww] == bv && iredw[ww] < bi)) {
                bv = fredw[ww]; bi = iredw[ww];
            }
        }
        s_anchor = bi;
        g_pwa[b] = U.g.pw[bi];
    }
    __syncthreads();
    int anchor = s_anchor;
    int ai = anchor / HH, aj = anchor % HH;

    // sv = sum_s pw*(dist,ang); Pp/Pn = sum pw^2 by sign
    float sv0 = 0.f, sv1 = 0.f, Pp = 0.f, Pn = 0.f;
    const float PI_F = 3.14159265358979323846f;
    for (int s = tid; s < SS; s += 256) {
        int i = s / HH, j = s - i * HH;
        float rx = (float)(i - ai) / 28.0f;
        float ry = (float)(j - aj) / 28.0f;
        float dist = sqrtf(rx * rx + ry * ry);
        float ang = (atan2f(ry, rx) / PI_F + 1.0f) / 2.0f;
        float p = U.g.pw[s];
        sv0 += p * dist;
        sv1 += p * ang;
        if (p > 0.f) Pp += p * p;
        else if (p < 0.f) Pn += p * p;
    }
    #pragma unroll
    for (int o = 16; o > 0; o >>= 1) {
        sv0 += __shfl_down_sync(0xffffffffu, sv0, o);
        sv1 += __shfl_down_sync(0xffffffffu, sv1, o);
        Pp  += __shfl_down_sync(0xffffffffu, Pp, o);
        Pn  += __shfl_down_sync(0xffffffffu, Pn, o);
    }
    if (l == 0) qredw[w] = make_float4(sv0, sv1, Pp, Pn);
    __syncthreads();
    if (tid == 0) {
        float4 t4 = qredw[0];
        #pragma unroll
        for (int ww = 1; ww < 8; ww++) {
            t4.x += qredw[ww].x; t4.y += qredw[ww].y;
            t4.z += qredw[ww].z; t4.w += qredw[ww].w;
        }
        s_sv0 = t4.x; s_sv1 = t4.y; s_Pp = t4.z; s_Pn = t4.w;
    }
    __syncthreads();
    float vsv0 = s_sv0, vsv1 = s_sv1, vPp = s_Pp, vPn = s_Pn;

    // u[j] = v1[j]*(v1>0 ? Pp : Pn), v1 = sv @ w1
    for (int j = tid; j < 512; j += 256) {
        float v1 = vsv0 * w1[j] + vsv1 * w1[512 + j];
        g_u[b * 512 + j] = v1 * (v1 > 0.f ? vPp : vPn);
    }

    // 3x3 [1,2,1;2,4,2;1,2,1] conv on counts -> keys with count in top byte
    for (int s = tid; s < SS; s += 256) {
        int i = s / HH, j = s - i * HH;
        int acc = 0;
        #pragma unroll
        for (int di = -1; di <= 1; di++) {
            int ii = i + di;
            if (ii < 0 || ii >= HH) continue;
            #pragma unroll
            for (int dj = -1; dj <= 1; dj++) {
                int jj = j + dj;
                if (jj < 0 || jj >= HH) continue;
                int wgt = (2 - (di < 0 ? -di : di)) * (2 - (dj < 0 ? -dj : dj));
                acc += wgt * U.g.cc[ii * HH + jj];
            }
        }
        U.g.keys[s] = ((unsigned)acc << 24) | ((unsigned)(1023 - s) << 14);
    }
    if (tid == 0) sel_cnt = 0;
    __syncthreads();

    unsigned KT; int krem;
    radix_select_desc(U.g.keys, SS, SEL, &KT, &krem);  // keys unique

    for (int s = tid; s < SS; s += 256) {
        if (U.g.keys[s] >= KT) {
            int p = atomicAdd(&sel_cnt, 1);
            sel_list[p] = U.g.keys[s];
        }
    }
    __syncthreads();
    if (tid < SEL) {
        unsigned mk = sel_list[tid];
        int r = 0;
        for (int m = 0; m < SEL; m++) r += (sel_list[m] > mk) ? 1 : 0;
        g_patchidx[b * 64 + r] = 1024 - (int)((mk >> 14) & 1023u);
    }
}

// ---------------------------------------------------------------------------
// Finish kernel: blocks 0..47 = w2 matvec with float4 loads + 8-way j split
// (b = blk/6, 128-col chunk = blk%6). Blocks >= 48 gather the selected rows.
// ---------------------------------------------------------------------------
#define MVB 48

__global__ void __launch_bounds__(256) finish_kernel(const float4* __restrict__ hid4,
                                                     float4* __restrict__ out4,
                                                     const float4* __restrict__ w2_4,
                                                     int SEL, int gatherTot) {
    int blk = blockIdx.x;
    int tid = threadIdx.x;
    const int D4 = DD / 4;        // 192 float4 per w2 row / out row
    const int ND4 = NN * D4;
    const int HS4 = BB * ND4;

    if (blk < MVB) {
        __shared__ float  su[512];
        __shared__ float4 red4[256];
        int b = blk / 6, kc = blk - b * 6;       // kc: chunk of 128 cols = 32 float4
        su[tid] = g_u[b * 512 + tid];
        su[256 + tid] = g_u[b * 512 + 256 + tid];
        __syncthreads();

        int fcol = tid & 31;                     // float4 column within chunk
        int jc = tid >> 5;                       // 0..7 -> j in [jc*64, jc*64+64)
        const float4* wp = w2_4 + kc * 32 + fcol;
        float4 acc = make_float4(0.f, 0.f, 0.f, 0.f);
        int j0 = jc * 64;
        #pragma unroll 8
        for (int j = j0; j < j0 + 64; j++) {
            float uj = su[j];
            float4 wv = wp[j * D4];
            acc.x += uj * wv.x; acc.y += uj * wv.y;
            acc.z += uj * wv.z; acc.w += uj * wv.w;
        }
        red4[tid] = acc;
        __syncthreads();
        if (tid < 32) {
            float4 s = red4[tid];
            #pragma unroll
            for (int p = 1; p < 8; p++) {
                float4 t = red4[p * 32 + tid];
                s.x += t.x; s.y += t.y; s.z += t.z; s.w += t.w;
            }
            float pwa = g_pwa[b];
            float4 o;
            o.x = pwa * s.x; o.y = pwa * s.y; o.z = pwa * s.z; o.w = pwa * s.w;
            o.x = (o.x > 0.f) ? o.x : 0.2f * o.x;
            o.y = (o.y > 0.f) ? o.y : 0.2f * o.y;
            o.z = (o.z > 0.f) ? o.z : 0.2f * o.z;
            o.w = (o.w > 0.f) ? o.w : 0.2f * o.w;
            int idx = b * ND4 + kc * 32 + tid;   // row 0 of batch b
            float4 h = hid4[idx];
            h.x += o.x; h.y += o.y; h.z += o.z; h.w += o.w;
            out4[idx] = h;
        }
        return;
    }

    int q = (blk - MVB) * 512 + tid;
    int perb = SEL * D4;
    #pragma unroll
    for (int rep = 0; rep < 2; rep++) {
        int qq = q + rep * 256;
        if (qq < gatherTot) {
            int b = qq / perb;
            int r = qq - b * perb;
            int i = r / D4;
            int k4 = r - i * D4;
            int rowi = g_patchidx[b * 64 + i];
            out4[HS4 + qq] = hid4[(b * NN + rowi) * D4 + k4];
        }
    }
}

// ---------------------------------------------------------------------------
extern "C" void kernel_launch(void* const* d_in, const int* in_sizes, int n_in,
                              void* d_out, int out_size) {
    const float* hidden = (const float*)d_in[0];
    const float* x      = (const float*)d_in[1];
    const float* w1     = (const float*)d_in[2];
    const float* w2     = (const float*)d_in[3];
    int SEL = (out_size - BB * NN * DD) / (BB * DD);

    const int D4 = DD / 4, ND4 = NN * D4;
    int copyA = BB * (ND4 - D4);               // rows 1..784 float4s
    int NC    = (copyA + 2047) / 2048;         // 8 float4 per thread
    fused_kernel<<<NTOPK + NC, 256>>>(x, w1, (const float4*)hidden,
                                      (float4*)d_out, SEL, copyA);

    int gatherTot = BB * SEL * D4;
    int NG = (gatherTot + 511) / 512;
    finish_kernel<<<MVB + NG, 256>>>((const float4*)hidden, (float4*)d_out,
                                     (const float4*)w2, SEL, gatherTot);
}